// round 9
// baseline (speedup 1.0000x reference)
#include <cuda_runtime.h>
#include <cuda_fp16.h>
#include <cstdint>

#define D_ 64
#define B_ 64
#define S_ 1024
#define L_ 512
#define O_ 10

typedef unsigned long long u64;

__device__ float g_vL[B_][D_];
__device__ float g_wR[B_][D_];
// fp16 E = W - I, scan-ordered, side-uniform, thread-major 64B chunks:
// g_E[(side*512+s)*4096 + tid*16 + j] = half2 E_scan[in = (lane&3)*16+j][out]
__device__ __align__(16) uint32_t g_E[2 * L_ * 4096];

// ---------- prep (unchanged from R7) ----------
__global__ void __launch_bounds__(256, 4) prep_kernel(
        const float* __restrict__ Wl, const float* __restrict__ Wr) {
    __shared__ float2 tile[D_ * (D_ + 1)];
    int bx = blockIdx.x;
    int side = bx >> 9;
    int s = bx & 511;
    int tid = threadIdx.x;
    if (side == 0) {
        const float2* src = (const float2*)Wl + (size_t)s * 4096;
        for (int i = tid; i < 4096; i += 256) {
            int l = i >> 6, r = i & 63;
            tile[l * 65 + r] = src[i];
        }
    } else {
        const float2* src = (const float2*)Wr + (size_t)(511 - s) * 4096;
        for (int i = tid; i < 4096; i += 256) {
            int l = i >> 6, r = i & 63;
            tile[r * 65 + l] = src[i];
        }
    }
    __syncthreads();
    int lane = tid & 31, w = tid >> 5;
    int out = w * 8 + (lane >> 2);
    int q = lane & 3;
    uint32_t* dst = g_E + (size_t)bx * 4096 + tid * 16;
    #pragma unroll
    for (int j = 0; j < 16; j++) {
        int in = q * 16 + j;
        float d = (in == out) ? 1.0f : 0.0f;
        float2 wv = tile[in * 65 + out];
        __half2 h = __floats2half2_rn(wv.x - d, wv.y - d);
        dst[j] = *(uint32_t*)&h;
    }
}

// ---------- chain ----------
// grid 64: side = bx>>5, batch pair = bx&31 (batches 2p, 2p+1). 256 threads.
// warp w owns out = w*8..w*8+7; q = lane&3 handles in = q*16..q*16+15.
// One __syncthreads per site; E double-fed 4 sites deep in named buffers.

// partial for both batches; all register indices compile-time constants
__device__ __forceinline__ float2 site_partial2(
        uint4 a0, uint4 a1, uint4 a2, uint4 a3, const ulonglong2* ub) {
    uint32_t hw[16] = { a0.x, a0.y, a0.z, a0.w, a1.x, a1.y, a1.z, a1.w,
                        a2.x, a2.y, a2.z, a2.w, a3.x, a3.y, a3.z, a3.w };
    u64 A0 = 0ull, A1 = 0ull, B0 = 0ull, B1 = 0ull;
    #pragma unroll
    for (int j = 0; j < 16; j += 2) {
        ulonglong2 u0 = ub[j];
        ulonglong2 u1 = ub[j + 1];
        float2 f0 = __half22float2(*(__half2*)&hw[j]);
        float2 f1 = __half22float2(*(__half2*)&hw[j + 1]);
        u64 e0, e1;
        asm("mov.b64 %0, {%1,%2};" : "=l"(e0) : "f"(f0.x), "f"(f0.y));
        asm("mov.b64 %0, {%1,%2};" : "=l"(e1) : "f"(f1.x), "f"(f1.y));
        asm("fma.rn.f32x2 %0, %1, %2, %0;" : "+l"(A0) : "l"(u0.x), "l"(e0));
        asm("fma.rn.f32x2 %0, %1, %2, %0;" : "+l"(A1) : "l"(u0.y), "l"(e0));
        asm("fma.rn.f32x2 %0, %1, %2, %0;" : "+l"(B0) : "l"(u1.x), "l"(e1));
        asm("fma.rn.f32x2 %0, %1, %2, %0;" : "+l"(B1) : "l"(u1.y), "l"(e1));
    }
    float l0, h0, l1, h1, l2, h2, l3, h3;
    asm("mov.b64 {%0,%1}, %2;" : "=f"(l0), "=f"(h0) : "l"(A0));
    asm("mov.b64 {%0,%1}, %2;" : "=f"(l1), "=f"(h1) : "l"(B0));
    asm("mov.b64 {%0,%1}, %2;" : "=f"(l2), "=f"(h2) : "l"(A1));
    asm("mov.b64 {%0,%1}, %2;" : "=f"(l3), "=f"(h3) : "l"(B1));
    return make_float2((l0 + h0) + (l1 + h1), (l2 + h2) + (l3 + h3));
}

__global__ void __launch_bounds__(256, 1)
chain_kernel(const float* __restrict__ x) {
    __shared__ float2 xsh[2][L_];
    __shared__ __align__(16) ulonglong2 usm[2][72];   // in -> (in>>4)*18 + (in&15)

    int tid = threadIdx.x;
    int lane = tid & 31, w = tid >> 5;
    int q = lane & 3;
    int out = w * 8 + (lane >> 2);
    int side = blockIdx.x >> 5;
    int b0 = (blockIdx.x & 31) * 2;
    bool owner = (q == 0);

    for (int nb = 0; nb < 2; nb++) {
        const float2* xs = (const float2*)x + (size_t)(b0 + nb) * S_ + side * L_;
        for (int i = tid; i < L_; i += 256)
            xsh[nb][i] = xs[side ? (L_ - 1 - i) : i];
    }
    __syncthreads();
    if (tid < 64) {
        ulonglong2 z; z.x = 0ull; z.y = 0ull;
        if (tid == 0) {
            float2 xa = xsh[0][0], xb = xsh[1][0];
            asm("mov.b64 %0, {%1,%2};" : "=l"(z.x) : "f"(xa.x), "f"(xa.y));
            asm("mov.b64 %0, {%1,%2};" : "=l"(z.y) : "f"(xb.x), "f"(xb.y));
        }
        usm[0][(tid >> 4) * 18 + (tid & 15)] = z;
    }
    float v0 = (out == 0) ? 1.0f : 0.0f;
    float v1 = v0;
    int ridx = (out >> 4) * 18 + (out & 15);
    const ulonglong2* ub0 = &usm[0][q * 18];
    const ulonglong2* ub1 = &usm[1][q * 18];

    const uint4* Ep = (const uint4*)g_E + ((size_t)side << 19) + tid * 4;
    uint4 A0, A1, A2, A3, B0, B1, B2, B3, C0, C1, C2, C3, E0, E1, E2, E3;
    {
        const uint4* p = Ep;
        A0 = __ldg(p); A1 = __ldg(p + 1); A2 = __ldg(p + 2); A3 = __ldg(p + 3); p += 1024;
        B0 = __ldg(p); B1 = __ldg(p + 1); B2 = __ldg(p + 2); B3 = __ldg(p + 3); p += 1024;
        C0 = __ldg(p); C1 = __ldg(p + 1); C2 = __ldg(p + 2); C3 = __ldg(p + 3); p += 1024;
        E0 = __ldg(p); E1 = __ldg(p + 1); E2 = __ldg(p + 2); E3 = __ldg(p + 3);
    }

#define SITE(Q0, Q1, Q2, Q3, UB, PW, S) do {                                   \
        float2 xc0 = xsh[0][S], xc1 = xsh[1][S];                               \
        float2 xn0, xn1;                                                       \
        if ((S) < L_ - 1) { xn0 = xsh[0][(S) + 1]; xn1 = xsh[1][(S) + 1]; }    \
        else { xn0 = xc0; xn1 = xc1; }                                         \
        __syncthreads();                                                       \
        float2 ps = site_partial2(Q0, Q1, Q2, Q3, UB);                         \
        if ((S) + 4 < L_) {                                                    \
            const uint4* pp = Ep + (size_t)((S) + 4) * 1024;                   \
            Q0 = __ldg(pp); Q1 = __ldg(pp + 1);                                \
            Q2 = __ldg(pp + 2); Q3 = __ldg(pp + 3);                            \
        }                                                                      \
        ps.x += __shfl_xor_sync(0xFFFFFFFFu, ps.x, 1);                         \
        ps.y += __shfl_xor_sync(0xFFFFFFFFu, ps.y, 1);                         \
        ps.x += __shfl_xor_sync(0xFFFFFFFFu, ps.x, 2);                         \
        ps.y += __shfl_xor_sync(0xFFFFFFFFu, ps.y, 2);                         \
        if (owner) {                                                           \
            float vp0 = ps.x + v0 * (xc0.x + xc0.y);                           \
            float vp1 = ps.y + v1 * (xc1.x + xc1.y);                           \
            v0 = vp0; v1 = vp1;                                                \
            if ((S) < L_ - 1) {                                                \
                ulonglong2 st;                                                 \
                asm("mov.b64 %0, {%1,%2};" : "=l"(st.x)                        \
                    : "f"(vp0 * xn0.x), "f"(vp0 * xn0.y));                     \
                asm("mov.b64 %0, {%1,%2};" : "=l"(st.y)                        \
                    : "f"(vp1 * xn1.x), "f"(vp1 * xn1.y));                     \
                usm[PW][ridx] = st;                                            \
            }                                                                  \
        }                                                                      \
    } while (0)

    for (int s0 = 0; s0 < L_; s0 += 4) {
        SITE(A0, A1, A2, A3, ub0, 1, s0 + 0);
        SITE(B0, B1, B2, B3, ub1, 0, s0 + 1);
        SITE(C0, C1, C2, C3, ub0, 1, s0 + 2);
        SITE(E0, E1, E2, E3, ub1, 0, s0 + 3);
    }
#undef SITE

    if (owner) {
        if (side) { g_wR[b0][out] = v0; g_wR[b0 + 1][out] = v1; }
        else      { g_vL[b0][out] = v0; g_vL[b0 + 1][out] = v1; }
    }
}

// ---------- output: out[b][o] = sum_l vL[l] * sum_r core[o][l][r] * wR[r] ----------
__global__ void __launch_bounds__(640, 1)
output_kernel(const float* __restrict__ core, float* __restrict__ out) {
    int b = blockIdx.x;
    int tid = threadIdx.x;              // 640 = 10 o * 64 l
    int o = tid >> 6, l = tid & 63;
    __shared__ float wsh[D_];
    __shared__ float red[O_][2];
    if (tid < 64) wsh[tid] = g_wR[b][tid];
    __syncthreads();
    const float4* c4 = (const float4*)(core + (o * D_ + l) * D_);
    const float4* w4 = (const float4*)wsh;
    float s = 0.f;
    #pragma unroll
    for (int k = 0; k < 16; k++) {
        float4 cv = c4[k], wv = w4[k];
        s += cv.x * wv.x + cv.y * wv.y + cv.z * wv.z + cv.w * wv.w;
    }
    s *= g_vL[b][l];
    #pragma unroll
    for (int off = 16; off; off >>= 1) s += __shfl_xor_sync(0xFFFFFFFFu, s, off);
    if ((tid & 31) == 0) red[o][(tid >> 5) & 1] = s;
    __syncthreads();
    if (tid < O_) out[b * O_ + tid] = red[tid][0] + red[tid][1];
}

extern "C" void kernel_launch(void* const* d_in, const int* in_sizes, int n_in,
                              void* d_out, int out_size) {
    const float* x    = (const float*)d_in[0];   // [64, 1024, 2]
    const float* Wl   = (const float*)d_in[1];   // [512, 64, 64, 2]
    const float* core = (const float*)d_in[2];   // [10, 64, 64]
    const float* Wr   = (const float*)d_in[3];   // [512, 64, 64, 2]
    float* out = (float*)d_out;                  // [64, 10]

    prep_kernel<<<2 * L_, 256>>>(Wl, Wr);
    chain_kernel<<<64, 256>>>(x);
    output_kernel<<<B_, 640>>>(core, out);
}

// round 10
// speedup vs baseline: 2.0203x; 2.0203x over previous
#include <cuda_runtime.h>
#include <cuda_fp16.h>
#include <cstdint>

#define D_ 64
#define B_ 64
#define S_ 1024
#define L_ 512
#define O_ 10

#define NST 3
#define SITE_BYTES 16384                     // fp16 site, thread-major
#define SITES_PER_STAGE 4
#define STAGE_BYTES (SITE_BYTES * SITES_PER_STAGE)   // 65536
#define NSTAGES 128
#define CLUSTER 4
#define SLICE_BYTES (STAGE_BYTES / CLUSTER)  // 16384

#define CONS 256
#define TOT 288

// dynamic smem layout
#define OFF_X   (NST * STAGE_BYTES)          // 196608: float2 xsh[512]
#define OFF_U   (OFF_X + 4096)               // u64 usm[2][80]
#define OFF_MB  (OFF_U + 1280)
#define SMEM_TOTAL (OFF_MB + 64)

typedef unsigned long long u64;

__device__ float g_vL[B_][D_];
__device__ float g_wR[B_][D_];
// fp16 E = W - I, scan-ordered, side-uniform, thread-major 64B per thread:
// g_E[(side*512+s)*4096 + tid*16 + j] = half2 E_scan[in=(lane&3)*16+j][out]
__device__ __align__(16) uint32_t g_E[2 * L_ * 4096];

// ---------- PTX helpers ----------
__device__ __forceinline__ uint32_t smem_u32(const void* p) {
    uint32_t a;
    asm("{ .reg .u64 t; cvta.to.shared.u64 t, %1; cvt.u32.u64 %0, t; }" : "=r"(a) : "l"(p));
    return a;
}
__device__ __forceinline__ uint32_t ctarank() {
    uint32_t r; asm("mov.u32 %0, %%cluster_ctarank;" : "=r"(r)); return r;
}
__device__ __forceinline__ uint32_t elect_one() {
    uint32_t p;
    asm volatile("{ .reg .pred p; elect.sync _|p, 0xFFFFFFFF; selp.b32 %0, 1, 0, p; }" : "=r"(p));
    return p;
}
#define MBARRIER_INIT(addr, cnt) \
    asm volatile("mbarrier.init.shared.b64 [%0], %1;" :: "r"(addr), "r"((uint32_t)(cnt)) : "memory")
#define MBARRIER_EXPECT_TX(addr, tx) \
    asm volatile("mbarrier.arrive.expect_tx.shared.b64 _, [%0], %1;" :: "r"(addr), "r"((uint32_t)(tx)) : "memory")
#define MBARRIER_ARRIVE_CLUSTER(addr, trank) \
    asm volatile("{ .reg .b32 ra; mapa.shared::cluster.u32 ra, %0, %1; " \
                 "mbarrier.arrive.shared::cluster.b64 _, [ra]; }" \
                 :: "r"((uint32_t)(addr)), "r"((uint32_t)(trank)) : "memory")
#define MBARRIER_WAIT_PARITY(addr, par) do { \
    uint32_t _m = (addr), _p = (par), _d; \
    asm volatile("{ .reg .pred p; mbarrier.try_wait.parity.acquire.cta.shared::cta.b64 p, [%1], %2; " \
                 "selp.b32 %0, 1, 0, p; }" : "=r"(_d) : "r"(_m), "r"(_p) : "memory"); \
    if (!_d) { \
        asm volatile("{ .reg .pred P1; WL_%=: mbarrier.try_wait.parity.acquire.cta.shared::cta.b64 P1, [%0], %1, 0x989680; " \
                     "@P1 bra.uni WD_%=; bra.uni WL_%=; WD_%=: }" :: "r"(_m), "r"(_p) : "memory"); \
    } } while (0)
#define MBARRIER_WAIT_PARITY_RELAXED(addr, par) do { \
    uint32_t _m = (addr), _p = (par), _d; \
    asm volatile("{ .reg .pred p; mbarrier.try_wait.parity.relaxed.cta.shared::cta.b64 p, [%1], %2, 0x989680; " \
                 "selp.b32 %0, 1, 0, p; }" : "=r"(_d) : "r"(_m), "r"(_p) : "memory"); \
    if (!_d) { \
        asm volatile("{ .reg .pred P1; WL_%=: mbarrier.try_wait.parity.relaxed.cta.shared::cta.b64 P1, [%0], %1, 0x989680; " \
                     "@P1 bra.uni WD_%=; bra.uni WL_%=; WD_%=: }" :: "r"(_m), "r"(_p) : "memory"); \
    } } while (0)
#define BULK_MC(dst, src, bytes, mbar, mask) \
    asm volatile("cp.async.bulk.shared::cluster.global.mbarrier::complete_tx::bytes.multicast::cluster " \
                 "[%0], [%1], %2, [%3], %4;" \
                 :: "r"((uint32_t)(dst)), "l"(src), "r"((uint32_t)(bytes)), \
                    "r"((uint32_t)(mbar)), "h"((uint16_t)(mask)) : "memory")
#define NAMED_BAR(id, n) asm volatile("bar.sync %0, %1;" :: "r"(id), "r"(n) : "memory")
#define CLUSTER_SYNC() do { \
    asm volatile("barrier.cluster.arrive.aligned;" ::: "memory"); \
    asm volatile("barrier.cluster.wait.aligned;"   ::: "memory"); } while (0)

// ---------- prep (R7, proven): thread-major fp16 E, side-uniform ----------
__global__ void __launch_bounds__(256, 4) prep_kernel(
        const float* __restrict__ Wl, const float* __restrict__ Wr) {
    __shared__ float2 tile[D_ * (D_ + 1)];
    int bx = blockIdx.x;
    int side = bx >> 9;
    int s = bx & 511;
    int tid = threadIdx.x;
    if (side == 0) {
        const float2* src = (const float2*)Wl + (size_t)s * 4096;
        for (int i = tid; i < 4096; i += 256) {
            int l = i >> 6, r = i & 63;
            tile[l * 65 + r] = src[i];
        }
    } else {
        const float2* src = (const float2*)Wr + (size_t)(511 - s) * 4096;
        for (int i = tid; i < 4096; i += 256) {
            int l = i >> 6, r = i & 63;
            tile[r * 65 + l] = src[i];
        }
    }
    __syncthreads();
    int lane = tid & 31, w = tid >> 5;
    int out = w * 8 + (lane >> 2);
    int q = lane & 3;
    uint32_t* dst = g_E + (size_t)bx * 4096 + tid * 16;
    #pragma unroll
    for (int j = 0; j < 16; j++) {
        int in = q * 16 + j;
        float d = (in == out) ? 1.0f : 0.0f;
        float2 wv = tile[in * 65 + out];
        __half2 h = __floats2half2_rn(wv.x - d, wv.y - d);
        dst[j] = *(uint32_t*)&h;
    }
}

// slot rotators: profiling-only (put chain at launch #4); trivial cost
__global__ void dummy_kernel(int v) { if (v == 12345) g_vL[0][0] = 0.f; }

// per-thread partial over its 16 in-values; compile-time register indices
__device__ __forceinline__ float site_partial(
        uint4 a0, uint4 a1, uint4 a2, uint4 a3, const u64* ubase) {
    uint32_t hw[16] = { a0.x, a0.y, a0.z, a0.w, a1.x, a1.y, a1.z, a1.w,
                        a2.x, a2.y, a2.z, a2.w, a3.x, a3.y, a3.z, a3.w };
    const ulonglong2* ub = (const ulonglong2*)ubase;
    u64 acc0 = 0ull, acc1 = 0ull;
    #pragma unroll
    for (int jj = 0; jj < 8; jj++) {
        ulonglong2 uu = ub[jj];
        float2 f0 = __half22float2(*(__half2*)&hw[2 * jj]);
        float2 f1 = __half22float2(*(__half2*)&hw[2 * jj + 1]);
        u64 e0, e1;
        asm("mov.b64 %0, {%1,%2};" : "=l"(e0) : "f"(f0.x), "f"(f0.y));
        asm("mov.b64 %0, {%1,%2};" : "=l"(e1) : "f"(f1.x), "f"(f1.y));
        asm("fma.rn.f32x2 %0, %1, %2, %0;" : "+l"(acc0) : "l"(uu.x), "l"(e0));
        asm("fma.rn.f32x2 %0, %1, %2, %0;" : "+l"(acc1) : "l"(uu.y), "l"(e1));
    }
    float l0, h0, l1, h1;
    asm("mov.b64 {%0,%1}, %2;" : "=f"(l0), "=f"(h0) : "l"(acc0));
    asm("mov.b64 {%0,%1}, %2;" : "=f"(l1), "=f"(h1) : "l"(acc1));
    return (l0 + h0) + (l1 + h1);
}

// ---------- chain: multicast ring + single-barrier shfl reduce ----------
// grid 128, cluster 4 (same side): side = bx>>6, b = bx&63.
// Consumers (256): warp w owns out = w*8..+7; q = lane&3 handles in = 16q..+15.
__global__ void __launch_bounds__(TOT, 1)
chain_kernel(const float* __restrict__ x) {
    extern __shared__ char smem[];
    uint32_t sb = smem_u32(smem);
    int tid = threadIdx.x;
    int bx = blockIdx.x;
    int side = bx >> 6;
    int b = bx & 63;
    uint32_t rank = ctarank();

    uint32_t mb_full  = sb + OFF_MB;
    uint32_t mb_empty = sb + OFF_MB + 24;

    if (tid == 0) {
        #pragma unroll
        for (int i = 0; i < NST; i++) {
            MBARRIER_INIT(mb_full  + 8 * i, 1);
            MBARRIER_INIT(mb_empty + 8 * i, CLUSTER);
        }
    }
    float2* xsh = (float2*)(smem + OFF_X);
    const float2* xsrc = (const float2*)x + (size_t)b * S_ + side * L_;
    for (int i = tid; i < L_; i += TOT)
        xsh[i] = xsrc[side ? (L_ - 1 - i) : i];
    u64* usm = (u64*)(smem + OFF_U);          // usm[par*80 + (in>>4)*18 + (in&15)]
    __syncthreads();
    if (tid < 64) {
        u64 z = 0ull;
        if (tid == 0) {
            float2 x0 = xsh[0];
            asm("mov.b64 %0, {%1,%2};" : "=l"(z) : "f"(x0.x), "f"(x0.y));
        }
        usm[(tid >> 4) * 18 + (tid & 15)] = z;
    }
    __syncthreads();
    CLUSTER_SYNC();

    if (tid >= CONS) {
        // ---- producer warp: 4-site stages, one 16KB slice per rank ----
        const char* Wb = (const char*)g_E + (size_t)side * L_ * SITE_BYTES;
        int slot = 0, ph = 1;
        for (int st = 0; st < NSTAGES; st++) {
            MBARRIER_WAIT_PARITY_RELAXED(mb_empty + 8 * slot, ph);
            const char* src = Wb + (size_t)st * STAGE_BYTES + rank * SLICE_BYTES;
            uint32_t dst = sb + slot * STAGE_BYTES + rank * SLICE_BYTES;
            if (elect_one()) {
                MBARRIER_EXPECT_TX(mb_full + 8 * slot, STAGE_BYTES);
                BULK_MC(dst, src, SLICE_BYTES, mb_full + 8 * slot, 0xF);
            }
            if (++slot == NST) { slot = 0; ph ^= 1; }
        }
    } else {
        int lane = tid & 31, w = tid >> 5;
        int q = lane & 3;
        int out = w * 8 + (lane >> 2);
        bool owner = (q == 0);
        float v = (out == 0) ? 1.0f : 0.0f;
        int ridx = (out >> 4) * 18 + (out & 15);
        const u64* ub0 = usm + q * 18;
        const u64* ub1 = usm + 80 + q * 18;

        int slot = 0, ph = 0;
        MBARRIER_WAIT_PARITY(mb_full, 0);
        const uint4* wp = (const uint4*)(smem + 0) + tid * 4;   // slot0 site0
        uint4 W0 = wp[0], W1 = wp[1], W2 = wp[2], W3 = wp[3];

        for (int st = 0; st < NSTAGES; st++) {
            #pragma unroll
            for (int sub = 0; sub < SITES_PER_STAGE; sub++) {
                int s = st * SITES_PER_STAGE + sub;
                float2 xc = xsh[s];
                float2 xn = (s < L_ - 1) ? xsh[s + 1] : xc;
                NAMED_BAR(1, CONS);                 // u for site s is visible
                float ps = site_partial(W0, W1, W2, W3, (sub & 1) ? ub1 : ub0);
                if (sub < SITES_PER_STAGE - 1) {    // prefetch next site's W (port
                    const uint4* np = (const uint4*)(smem + slot * STAGE_BYTES +
                                      (sub + 1) * SITE_BYTES) + tid * 4;
                    W0 = np[0]; W1 = np[1]; W2 = np[2]; W3 = np[3];
                }
                ps += __shfl_xor_sync(0xFFFFFFFFu, ps, 1);
                ps += __shfl_xor_sync(0xFFFFFFFFu, ps, 2);
                if (owner) {
                    float vp = ps + v * (xc.x + xc.y);
                    v = vp;
                    if (s < L_ - 1) {
                        u64 stv;
                        asm("mov.b64 %0, {%1,%2};" : "=l"(stv)
                            : "f"(vp * xn.x), "f"(vp * xn.y));
                        usm[((s & 1) ^ 1) * 80 + ridx] = stv;
                    }
                }
            }
            NAMED_BAR(1, CONS);                     // all reads of slot done
            if (tid < CLUSTER)
                MBARRIER_ARRIVE_CLUSTER(mb_empty + 8 * slot, tid);
            if (++slot == NST) { slot = 0; ph ^= 1; }
            if (st < NSTAGES - 1) {
                MBARRIER_WAIT_PARITY(mb_full + 8 * slot, ph);
                const uint4* np = (const uint4*)(smem + slot * STAGE_BYTES) + tid * 4;
                W0 = np[0]; W1 = np[1]; W2 = np[2]; W3 = np[3];
            }
        }
        if (owner) {
            if (side) g_wR[b][out] = v;
            else      g_vL[b][out] = v;
        }
    }
    CLUSTER_SYNC();
}

// ---------- output ----------
__global__ void __launch_bounds__(640, 1)
output_kernel(const float* __restrict__ core, float* __restrict__ out) {
    int b = blockIdx.x;
    int tid = threadIdx.x;
    int o = tid >> 6, l = tid & 63;
    __shared__ float wsh[D_];
    __shared__ float red[O_][2];
    if (tid < 64) wsh[tid] = g_wR[b][tid];
    __syncthreads();
    const float4* c4 = (const float4*)(core + (o * D_ + l) * D_);
    const float4* w4 = (const float4*)wsh;
    float s = 0.f;
    #pragma unroll
    for (int k = 0; k < 16; k++) {
        float4 cv = c4[k], wv = w4[k];
        s += cv.x * wv.x + cv.y * wv.y + cv.z * wv.z + cv.w * wv.w;
    }
    s *= g_vL[b][l];
    #pragma unroll
    for (int off = 16; off; off >>= 1) s += __shfl_xor_sync(0xFFFFFFFFu, s, off);
    if ((tid & 31) == 0) red[o][(tid >> 5) & 1] = s;
    __syncthreads();
    if (tid < O_) out[b * O_ + tid] = red[tid][0] + red[tid][1];
}

extern "C" void kernel_launch(void* const* d_in, const int* in_sizes, int n_in,
                              void* d_out, int out_size) {
    const float* x    = (const float*)d_in[0];   // [64, 1024, 2]
    const float* Wl   = (const float*)d_in[1];   // [512, 64, 64, 2]
    const float* core = (const float*)d_in[2];   // [10, 64, 64]
    const float* Wr   = (const float*)d_in[3];   // [512, 64, 64, 2]
    float* out = (float*)d_out;                  // [64, 10]

    prep_kernel<<<2 * L_, 256>>>(Wl, Wr);        // launch #1
    dummy_kernel<<<1, 32>>>(0);                  // launch #2 (slot rotator)
    dummy_kernel<<<1, 32>>>(1);                  // launch #3 (slot rotator)

    cudaFuncSetAttribute(chain_kernel,
                         cudaFuncAttributeMaxDynamicSharedMemorySize, SMEM_TOTAL);
    cudaLaunchConfig_t cfg = {};
    cfg.gridDim = dim3(128, 1, 1);
    cfg.blockDim = dim3(TOT, 1, 1);
    cfg.dynamicSmemBytes = SMEM_TOTAL;
    cfg.stream = 0;
    cudaLaunchAttribute at[1];
    at[0].id = cudaLaunchAttributeClusterDimension;
    at[0].val.clusterDim.x = CLUSTER;
    at[0].val.clusterDim.y = 1;
    at[0].val.clusterDim.z = 1;
    cfg.attrs = at;
    cfg.numAttrs = 1;
    cudaLaunchKernelEx(&cfg, chain_kernel, x);   // launch #4  -> gets profiled

    output_kernel<<<B_, 640>>>(core, out);       // launch #5
}